// round 4
// baseline (speedup 1.0000x reference)
#include <cuda_runtime.h>

#define NB 8
#define NS 4096
#define NH 8
#define ND 128
#define ROW (NH * ND)                 // 1024 floats per token-row
#define VPR (ROW / 4)                 // 256 float4 per row
#define MAX_TOTAL (NB * NS)           // 32768 rows per cache
#define CACHE_F (MAX_TOTAL * ROW)     // floats per cache
#define CACHE_V (MAX_TOTAL * VPR)     // 8388608 float4 per cache
#define TOTAL_V (2 * CACHE_V)         // 16777216 float4
#define THREADS 256
#define F4_PER_THREAD 8
#define F4_PER_WARP 256               // one full token-row per warp
#define WARPS_PER_BLOCK (THREADS / 32)
#define BLOCKS (TOTAL_V / (F4_PER_WARP * WARPS_PER_BLOCK))   // 8192

// Each warp owns exactly one token-row (256 float4 = 4KB). Lane l handles
// col = l + k*32, k=0..7: every LDG.128/STG.128 fully coalesced, 8 independent
// loads in flight per thread, one batch-search per thread. Streaming (.cs)
// hints since data is touched exactly once.
__global__ void __launch_bounds__(THREADS) pack_kernel(
    const float4* __restrict__ k_src,
    const float4* __restrict__ v_src,
    const int* __restrict__ seq_lens,
    float4* __restrict__ out)
{
    __shared__ int cs[NB + 1];
    if (threadIdx.x == 0) {
        int c = 0;
        cs[0] = 0;
        #pragma unroll
        for (int i = 0; i < NB; i++) { c += __ldg(seq_lens + i); cs[i + 1] = c; }
    }
    __syncthreads();

    if (blockIdx.x == 0 && threadIdx.x == 0) {
        float* seq_out = (float*)out + 2 * (long long)CACHE_F;  // [NB]
        float* cum_out = seq_out + NB;                           // [NB+1]
        #pragma unroll
        for (int i = 0; i < NB; i++) seq_out[i] = (float)(cs[i + 1] - cs[i]);
        #pragma unroll
        for (int i = 0; i <= NB; i++) cum_out[i] = (float)cs[i];
    }

    int lane = threadIdx.x & 31;
    int gw   = blockIdx.x * WARPS_PER_BLOCK + (threadIdx.x >> 5);
    int base = gw * F4_PER_WARP;                  // warp's first float4 index

    int which = (base >= CACHE_V) ? 1 : 0;        // whole warp in one cache
    int row   = (base - which * CACHE_V) >> 8;    // this warp's token-row

    float4 v[F4_PER_THREAD];
    if (row < cs[NB]) {
        int b = 0;
        #pragma unroll
        for (int bb = 1; bb < NB; bb++)
            if (row >= cs[bb]) b = bb;
        int t = row - cs[b];
        const float4* src = (which ? v_src : k_src)
                          + (long long)(b * NS + t) * VPR + lane;
        #pragma unroll
        for (int k = 0; k < F4_PER_THREAD; k++)
            v[k] = __ldcs(src + k * 32);          // 8 front-batched LDG.128
    } else {
        #pragma unroll
        for (int k = 0; k < F4_PER_THREAD; k++)
            v[k] = make_float4(0.f, 0.f, 0.f, 0.f);
    }

    float4* dst = out + base + lane;
    #pragma unroll
    for (int k = 0; k < F4_PER_THREAD; k++)
        __stcs(dst + k * 32, v[k]);
}

extern "C" void kernel_launch(void* const* d_in, const int* in_sizes, int n_in,
                              void* d_out, int out_size) {
    const float4* key_states   = (const float4*)d_in[0];
    const float4* value_states = (const float4*)d_in[1];
    const int*    seq_lens     = (const int*)d_in[2];

    pack_kernel<<<BLOCKS, THREADS>>>(key_states, value_states, seq_lens,
                                     (float4*)d_out);
}

// round 5
// speedup vs baseline: 1.0102x; 1.0102x over previous
#include <cuda_runtime.h>

#define NB 8
#define NS 4096
#define NH 8
#define ND 128
#define ROW (NH * ND)                 // 1024 floats per token-row
#define VPR (ROW / 4)                 // 256 float4 per row
#define MAX_TOTAL (NB * NS)           // 32768 rows per cache
#define CACHE_F (MAX_TOTAL * ROW)     // floats per cache
#define CACHE_V (MAX_TOTAL * VPR)     // 8388608 float4 per cache
#define TOTAL_V (2 * CACHE_V)         // 16777216 float4
#define THREADS 256
#define F4_PER_WARP 128               // 4 float4 per thread, warp-interleaved
#define WARPS_PER_BLOCK (THREADS / 32)
#define BLOCKS (TOTAL_V / (F4_PER_WARP * WARPS_PER_BLOCK))   // 16384

// R3 layout (best so far) + streaming cache hints.
// Each warp owns 128 consecutive float4 (2KB) = half a token-row; lane l
// handles base + {0,32,64,96} + l. Every LDG.128/STG.128 fully coalesced,
// 4 independent loads in flight per thread, one batch-search per thread.
__global__ void __launch_bounds__(THREADS) pack_kernel(
    const float4* __restrict__ k_src,
    const float4* __restrict__ v_src,
    const int* __restrict__ seq_lens,
    float4* __restrict__ out)
{
    __shared__ int cs[NB + 1];
    if (threadIdx.x == 0) {
        int c = 0;
        cs[0] = 0;
        #pragma unroll
        for (int i = 0; i < NB; i++) { c += __ldg(seq_lens + i); cs[i + 1] = c; }
    }
    __syncthreads();

    if (blockIdx.x == 0 && threadIdx.x == 0) {
        float* seq_out = (float*)out + 2 * (long long)CACHE_F;  // [NB]
        float* cum_out = seq_out + NB;                           // [NB+1]
        #pragma unroll
        for (int i = 0; i < NB; i++) seq_out[i] = (float)(cs[i + 1] - cs[i]);
        #pragma unroll
        for (int i = 0; i <= NB; i++) cum_out[i] = (float)cs[i];
    }

    int lane = threadIdx.x & 31;
    int gw   = blockIdx.x * WARPS_PER_BLOCK + (threadIdx.x >> 5);
    int base = gw * F4_PER_WARP;                  // warp's first float4 index

    int which = (base >= CACHE_V) ? 1 : 0;        // whole warp in one cache
    int j   = base - which * CACHE_V;
    int row = j >> 8;                              // token-row (shared by all 4 elems)
    int col = (j & (VPR - 1)) + lane;              // 0 or 128, plus lane

    float4 v0, v1, v2, v3;
    if (row < cs[NB]) {
        int b = 0;
        #pragma unroll
        for (int bb = 1; bb < NB; bb++)
            if (row >= cs[bb]) b = bb;
        int t = row - cs[b];
        const float4* src = (which ? v_src : k_src)
                          + (long long)(b * NS + t) * VPR + col;
        v0 = __ldcs(src +  0);
        v1 = __ldcs(src + 32);
        v2 = __ldcs(src + 64);
        v3 = __ldcs(src + 96);
    } else {
        v0 = v1 = v2 = v3 = make_float4(0.f, 0.f, 0.f, 0.f);
    }

    float4* dst = out + base + lane;
    __stcs(dst +  0, v0);
    __stcs(dst + 32, v1);
    __stcs(dst + 64, v2);
    __stcs(dst + 96, v3);
}

extern "C" void kernel_launch(void* const* d_in, const int* in_sizes, int n_in,
                              void* d_out, int out_size) {
    const float4* key_states   = (const float4*)d_in[0];
    const float4* value_states = (const float4*)d_in[1];
    const int*    seq_lens     = (const int*)d_in[2];

    pack_kernel<<<BLOCKS, THREADS>>>(key_states, value_states, seq_lens,
                                     (float4*)d_out);
}